// round 9
// baseline (speedup 1.0000x reference)
#include <cuda_runtime.h>
#include <cuda_bf16.h>
#include <cstdint>

// RNN-T joint network, 2 launches:
//  1) convert: fp32 -> bf16 (hi,lo) split images; block 0 zeroes flags.
//  2) fused kernel, grid = 640, occ 2 (fine-grained pipeline):
//       bid 0..127  : pred GEMM tile 32x128 -> g_pred, release flag.
//       bid 128..639: enc GEMM tile 32x128 -> smem; wait 2 pred flags;
//                     drain 1MB output brick with coalesced st.global.cs.
//     Small tiles => CTAs retire continuously => GEMM of later tiles
//     overlaps the DRAM drain of earlier ones (no 30us DRAM-idle ramp).

#define VOCAB 2048
#define KC    1536
#define NB    4
#define NT    256
#define NU    64
#define NPT   128                     // pred tiles
#define GRID  640

// -------- scratch (device globals; no allocations allowed) --------
__device__ __nv_bfloat16 g_Ac[1280 * KC];
__device__ __nv_bfloat16 g_Be[VOCAB * KC];
__device__ __nv_bfloat16 g_Bp[VOCAB * KC];
__device__ float g_pred[256 * VOCAB];
__device__ int   g_flags[NPT];        // pred tile (pt, n): pt*16 + n

// ---------------------------------------------------------------------------
// Stage 1: split-precision convert (proven) + flag reset
// ---------------------------------------------------------------------------
__global__ __launch_bounds__(256)
void convert_kernel(const float* __restrict__ enc,
                    const float* __restrict__ pred,
                    const float* __restrict__ W) {
    if (blockIdx.x == 0 && threadIdx.x < NPT) g_flags[threadIdx.x] = 0;
    int idx = blockIdx.x * 256 + threadIdx.x;

    float2 x;
    __nv_bfloat16* base;
    bool isA;
    if (idx < 262144) {
        x = ((const float2*)enc)[idx];
        int m = idx >> 8, k = (idx & 255) * 2;
        base = g_Ac + (size_t)m * KC + k;
        isA = true;
    } else if (idx < 327680) {
        int p = idx - 262144;
        x = ((const float2*)pred)[p];
        int m = 1024 + (p >> 8), k = (p & 255) * 2;
        base = g_Ac + (size_t)m * KC + k;
        isA = true;
    } else {
        int p = idx - 327680;
        x = ((const float2*)W)[p];
        int v = p >> 9, k = (p & 511) * 2;
        if (k < 512) base = g_Be + (size_t)v * KC + k;
        else         base = g_Bp + (size_t)v * KC + (k - 512);
        isA = false;
    }

    __nv_bfloat162 h, l;
    h.x = __float2bfloat16_rn(x.x);
    h.y = __float2bfloat16_rn(x.y);
    l.x = __float2bfloat16_rn(x.x - __bfloat162float(h.x));
    l.y = __float2bfloat16_rn(x.y - __bfloat162float(h.y));

    if (isA) {  // [hi | hi | lo]
        *(__nv_bfloat162*)(base)        = h;
        *(__nv_bfloat162*)(base +  512) = h;
        *(__nv_bfloat162*)(base + 1024) = l;
    } else {    // [hi | lo | hi]
        *(__nv_bfloat162*)(base)        = h;
        *(__nv_bfloat162*)(base +  512) = l;
        *(__nv_bfloat162*)(base + 1024) = h;
    }
}

// ---------------------------------------------------------------------------
// helpers
// ---------------------------------------------------------------------------
#define BK     64
#define STAGES 3
#define A_ST   4096                   // 32 rows * 128B
#define B_ST   16384                  // 128 rows * 128B
#define ST_SZ  (A_ST + B_ST)          // 20KB per stage
#define DSMEM  (STAGES * ST_SZ)       // 60KB (drain needs 50.7KB <= this)
#define PSTR   132                    // padded fp32 row stride for drain tiles

__device__ __forceinline__ uint32_t s2u(const void* p) {
    return (uint32_t)__cvta_generic_to_shared(p);
}
#define CPA16(s, g) asm volatile("cp.async.cg.shared.global [%0], [%1], 16;" :: "r"(s), "l"(g))
#define LDSM4(r0,r1,r2,r3,a) asm volatile( \
    "ldmatrix.sync.aligned.m8n8.x4.shared.b16 {%0,%1,%2,%3}, [%4];" \
    : "=r"(r0),"=r"(r1),"=r"(r2),"=r"(r3) : "r"(a))
#define MMA16816(c,a0,a1,a2,a3,b0,b1) asm volatile( \
    "mma.sync.aligned.m16n8k16.row.col.f32.bf16.bf16.f32 " \
    "{%0,%1,%2,%3},{%4,%5,%6,%7},{%8,%9},{%0,%1,%2,%3};" \
    : "+f"(c[0]),"+f"(c[1]),"+f"(c[2]),"+f"(c[3]) \
    : "r"(a0),"r"(a1),"r"(a2),"r"(a3),"r"(b0),"r"(b1))

__device__ __forceinline__ uint32_t swz(uint32_t row, uint32_t cb) {
    return row * 128 + (cb ^ ((row & 7) * 16));
}
__device__ __forceinline__ void stcs(float4* p, float4 v) {
    asm volatile("st.global.cs.v4.f32 [%0], {%1,%2,%3,%4};"
                 :: "l"(p), "f"(v.x), "f"(v.y), "f"(v.z), "f"(v.w));
}
__device__ __forceinline__ void wait_flag(const int* f) {
    int v;
    while (true) {
        asm volatile("ld.acquire.gpu.global.b32 %0, [%1];" : "=r"(v) : "l"(f));
        if (v) break;
        __nanosleep(200);
    }
}

// ---------------------------------------------------------------------------
// Fused kernel: 32x128 GEMM tiles; enc tiles drain their output brick.
// ---------------------------------------------------------------------------
__global__ __launch_bounds__(256, 2)
void fused_kernel(const float* __restrict__ bias, float* __restrict__ out) {
    extern __shared__ __align__(1024) char smem[];
    const uint32_t sb = s2u(smem);
    const int bid = blockIdx.x;
    const int tid = threadIdx.x;
    const int lane = tid & 31;
    const int wid  = tid >> 5;

    const bool is_pred = (bid < NPT);
    int m, n, b;
    const __nv_bfloat16 *gA, *gB;
    if (is_pred) {
        const int pt = bid >> 4; n = bid & 15;     // pt 0..7
        gA = g_Ac + (size_t)(1024 + pt * 32) * KC;
        gB = g_Bp + (size_t)(n * 128) * KC;
        m = pt;
        b = 0;
    } else {
        const int e = bid - NPT;
        m = e >> 4; n = e & 15;                    // m 0..31
        gA = g_Ac + (size_t)(m * 32) * KC;
        gB = g_Be + (size_t)(n * 128) * KC;
        b = m >> 3;
    }
    const int vbase = n * 128;

    // ---- cp.async staging: A 256 chunks (1/thr), B 1024 chunks (4/thr) ----
    const int raA = tid >> 3, jaA = (tid & 7) * 16;
    const uint32_t sA0 = swz(raA, jaA);
    const __nv_bfloat16* gA0 = gA + (size_t)raA * KC + jaA / 2;
    uint32_t sBo[4];
    const __nv_bfloat16* gBo[4];
    #pragma unroll
    for (int i = 0; i < 4; i++) {
        int cidx = tid + i * 256;
        int rr = cidx >> 3, jj = (cidx & 7) * 16;
        sBo[i] = swz(rr, jj);
        gBo[i] = gB + (size_t)rr * KC + jj / 2;
    }

    // ---- ldmatrix lane addresses (stage-relative) ----
    const uint32_t uA = swz(lane & 15, (lane >> 4) * 16);
    const uint32_t uB = swz(wid * 16 + ((lane >> 4) & 1) * 8 + (lane & 7),
                            ((lane >> 3) & 1) * 16) + A_ST;

    float c[2][2][4];
    #pragma unroll
    for (int i = 0; i < 2; i++)
        #pragma unroll
        for (int j = 0; j < 2; j++)
            #pragma unroll
            for (int e2 = 0; e2 < 4; e2++) c[i][j][e2] = 0.f;

    auto fill = [&](int s, int koff) {
        const uint32_t ab = sb + s * ST_SZ;
        const uint32_t bb = ab + A_ST;
        CPA16(ab + sA0, gA0 + koff);
        #pragma unroll
        for (int i = 0; i < 4; i++)
            CPA16(bb + sBo[i], gBo[i] + koff);
        asm volatile("cp.async.commit_group;");
    };

    fill(0, 0);
    fill(1, BK);

    const int NKT = KC / BK;   // 24
    int s = 0;
    for (int kt = 0; kt < NKT; kt++) {
        if (kt < NKT - 1) asm volatile("cp.async.wait_group 1;");
        else              asm volatile("cp.async.wait_group 0;");
        __syncthreads();

        if (kt + 2 < NKT) {
            int sn = s + 2; if (sn >= STAGES) sn -= STAGES;
            fill(sn, (kt + 2) * BK);
        }

        const uint32_t abase = sb + s * ST_SZ + uA;
        const uint32_t bbase = sb + s * ST_SZ + uB;
        #pragma unroll
        for (int kk = 0; kk < 4; kk++) {
            uint32_t a[2][4], bf[4];
            #pragma unroll
            for (int mi = 0; mi < 2; mi++)
                LDSM4(a[mi][0], a[mi][1], a[mi][2], a[mi][3],
                      (abase + mi * 2048) ^ (kk << 5));
            LDSM4(bf[0], bf[1], bf[2], bf[3], bbase ^ (kk << 5));
            #pragma unroll
            for (int mi = 0; mi < 2; mi++) {
                MMA16816(c[mi][0], a[mi][0], a[mi][1], a[mi][2], a[mi][3], bf[0], bf[1]);
                MMA16816(c[mi][1], a[mi][0], a[mi][1], a[mi][2], a[mi][3], bf[2], bf[3]);
            }
        }
        if (++s >= STAGES) s -= STAGES;
    }

    const int mrow0 = lane >> 2;                 // 0..7
    const int ncol0 = wid * 16 + (lane & 3) * 2; // within 128-col tile

    if (is_pred) {
        // ---- pred epilogue: frags -> g_pred, then release flag ----
        float* C = g_pred + (size_t)(m * 32) * VOCAB + vbase;
        #pragma unroll
        for (int mi = 0; mi < 2; mi++) {
            #pragma unroll
            for (int ni = 0; ni < 2; ni++) {
                float* p0 = &C[(size_t)(mrow0 + mi * 16)     * VOCAB + ncol0 + ni * 8];
                float* p1 = &C[(size_t)(mrow0 + mi * 16 + 8) * VOCAB + ncol0 + ni * 8];
                *(float2*)p0 = make_float2(c[mi][ni][0], c[mi][ni][1]);
                *(float2*)p1 = make_float2(c[mi][ni][2], c[mi][ni][3]);
            }
        }
        __threadfence();
        __syncthreads();
        if (tid == 0) atomicExch(&g_flags[bid], 1);
        return;
    }

    // ---- enc epilogue: frags -> smem, fetch pred tiles, drain output ----
    __syncthreads();                       // all LDSM done; safe to reuse smem
    float* enc_s  = (float*)smem;          // [32][PSTR]
    float* pred_s = enc_s + 32 * PSTR;     // [64][PSTR]

    #pragma unroll
    for (int mi = 0; mi < 2; mi++) {
        #pragma unroll
        for (int ni = 0; ni < 2; ni++) {
            float* p0 = &enc_s[(mrow0 + mi * 16)     * PSTR + ncol0 + ni * 8];
            float* p1 = &enc_s[(mrow0 + mi * 16 + 8) * PSTR + ncol0 + ni * 8];
            *(float2*)p0 = make_float2(c[mi][ni][0], c[mi][ni][1]);
            *(float2*)p1 = make_float2(c[mi][ni][2], c[mi][ni][3]);
        }
    }

    // need both pred tiles of this b (u rows 0..31 and 32..63), same n
    if (tid == 0)  wait_flag(&g_flags[(b * 2)     * 16 + n]);
    if (tid == 32) wait_flag(&g_flags[(b * 2 + 1) * 16 + n]);
    __syncthreads();

    // pred tile + bias -> smem: 64u x 128v = 2048 float4, 8/thread
    {
        const float* pg = g_pred + (size_t)(b * NU) * VOCAB + vbase;
        #pragma unroll
        for (int i = 0; i < 8; i++) {
            int e = tid + i * 256;
            int u = e >> 5, cc = e & 31;
            float4 p = *(const float4*)(pg + (size_t)u * VOCAB + cc * 4);
            float4 bv = *(const float4*)(bias + vbase + cc * 4);
            *(float4*)&pred_s[u * PSTR + cc * 4] =
                make_float4(p.x + bv.x, p.y + bv.y, p.z + bv.z, p.w + bv.w);
        }
    }
    __syncthreads();

    // drain: warp w -> t rows [w*4, w*4+4); u chunks of 4 cached in regs.
    const int col   = lane;
    const int tbase = (m & 7) * 32;
    float* ob = out + ((size_t)(b * NT + tbase) * NU) * VOCAB + vbase;

    #pragma unroll 1
    for (int uc = 0; uc < NU; uc += 4) {
        float4 p0 = *(float4*)&pred_s[(uc + 0) * PSTR + col * 4];
        float4 p1 = *(float4*)&pred_s[(uc + 1) * PSTR + col * 4];
        float4 p2 = *(float4*)&pred_s[(uc + 2) * PSTR + col * 4];
        float4 p3 = *(float4*)&pred_s[(uc + 3) * PSTR + col * 4];
        #pragma unroll
        for (int ti = 0; ti < 4; ti++) {
            const int t = wid * 4 + ti;
            float4 e = *(float4*)&enc_s[t * PSTR + col * 4];
            float4* orow = (float4*)(ob + ((size_t)t * NU + uc) * VOCAB);
            stcs(&orow[0 * (VOCAB / 4) + col],
                 make_float4(e.x + p0.x, e.y + p0.y, e.z + p0.z, e.w + p0.w));
            stcs(&orow[1 * (VOCAB / 4) + col],
                 make_float4(e.x + p1.x, e.y + p1.y, e.z + p1.z, e.w + p1.w));
            stcs(&orow[2 * (VOCAB / 4) + col],
                 make_float4(e.x + p2.x, e.y + p2.y, e.z + p2.z, e.w + p2.w));
            stcs(&orow[3 * (VOCAB / 4) + col],
                 make_float4(e.x + p3.x, e.y + p3.y, e.z + p3.z, e.w + p3.w));
        }
    }
}

// ---------------------------------------------------------------------------
extern "C" void kernel_launch(void* const* d_in, const int* in_sizes, int n_in,
                              void* d_out, int out_size) {
    const float* enc  = (const float*)d_in[0];
    const float* pred = (const float*)d_in[1];
    const float* W    = (const float*)d_in[2];
    const float* bias = (const float*)d_in[3];
    float* out = (float*)d_out;

    cudaFuncSetAttribute(fused_kernel,
                         cudaFuncAttributeMaxDynamicSharedMemorySize, DSMEM);

    convert_kernel<<<5376, 256>>>(enc, pred, W);
    fused_kernel<<<GRID, 256, DSMEM>>>(bias, out);
}

// round 10
// speedup vs baseline: 1.2009x; 1.2009x over previous
#include <cuda_runtime.h>
#include <cuda_fp16.h>
#include <cstdint>

// RNN-T joint network, 2 launches:
//  1) convert: fp32 -> fp16 (single image; fp16's 11 mantissa bits give
//     ~2e-4 aggregate GEMM error, inside the 1e-3 gate -> K=512, 3x less
//     GEMM work than the bf16 (hi,lo) split).
//  2) fused kernel, grid = 320 (one wave @ occ 2)  [round-7 structure]:
//       bid 0..63   : pred GEMM tile 64x128 -> g_pred, release flag.
//       bid 64..319 : enc GEMM tile 64x128 -> smem; wait 1 pred flag;
//                     drain 2MB output brick with coalesced st.global.cs.

#define VOCAB 2048
#define KC    512
#define NB    4
#define NT    256
#define NU    64

// -------- scratch (device globals; no allocations allowed) --------
__device__ __half g_Ac[1280 * KC];      // enc rows 0..1023, pred rows 1024..1279
__device__ __half g_Be[VOCAB * KC];
__device__ __half g_Bp[VOCAB * KC];
__device__ float  g_pred[256 * VOCAB];
__device__ int    g_flags[64];          // pred tile (pb, n): pb*16 + n

// ---------------------------------------------------------------------------
// Stage 1: fp32 -> fp16 convert + flag reset. 1376256 float2 pairs total.
// ---------------------------------------------------------------------------
__global__ __launch_bounds__(256)
void convert_kernel(const float* __restrict__ enc,
                    const float* __restrict__ pred,
                    const float* __restrict__ W) {
    if (blockIdx.x == 0 && threadIdx.x < 64) g_flags[threadIdx.x] = 0;
    int idx = blockIdx.x * 256 + threadIdx.x;

    float2 x;
    __half* base;
    if (idx < 262144) {                       // enc: 1024 rows x 256 pairs
        x = ((const float2*)enc)[idx];
        int m = idx >> 8, k = (idx & 255) * 2;
        base = g_Ac + (size_t)m * KC + k;
    } else if (idx < 327680) {                // pred: 256 rows x 256 pairs
        int p = idx - 262144;
        x = ((const float2*)pred)[p];
        int m = 1024 + (p >> 8), k = (p & 255) * 2;
        base = g_Ac + (size_t)m * KC + k;
    } else {                                  // W: 2048 rows x 512 pairs
        int p = idx - 327680;
        x = ((const float2*)W)[p];
        int v = p >> 9, k = (p & 511) * 2;
        if (k < 512) base = g_Be + (size_t)v * KC + k;
        else         base = g_Bp + (size_t)v * KC + (k - 512);
    }
    *(__half2*)base = __floats2half2_rn(x.x, x.y);
}

// ---------------------------------------------------------------------------
// helpers
// ---------------------------------------------------------------------------
#define BK     64
#define STAGES 3
#define A_ST   8192                   // 64 rows * 128B
#define B_ST   16384                  // 128 rows * 128B
#define ST_SZ  (A_ST + B_ST)          // 24KB per stage
#define DSMEM  (STAGES * ST_SZ)       // 72KB (drain needs 67.6KB <= this)
#define PSTR   132                    // padded fp32 row stride for drain tiles

__device__ __forceinline__ uint32_t s2u(const void* p) {
    return (uint32_t)__cvta_generic_to_shared(p);
}
#define CPA16(s, g) asm volatile("cp.async.cg.shared.global [%0], [%1], 16;" :: "r"(s), "l"(g))
#define LDSM4(r0,r1,r2,r3,a) asm volatile( \
    "ldmatrix.sync.aligned.m8n8.x4.shared.b16 {%0,%1,%2,%3}, [%4];" \
    : "=r"(r0),"=r"(r1),"=r"(r2),"=r"(r3) : "r"(a))
#define MMA16816(c,a0,a1,a2,a3,b0,b1) asm volatile( \
    "mma.sync.aligned.m16n8k16.row.col.f32.f16.f16.f32 " \
    "{%0,%1,%2,%3},{%4,%5,%6,%7},{%8,%9},{%0,%1,%2,%3};" \
    : "+f"(c[0]),"+f"(c[1]),"+f"(c[2]),"+f"(c[3]) \
    : "r"(a0),"r"(a1),"r"(a2),"r"(a3),"r"(b0),"r"(b1))

__device__ __forceinline__ uint32_t swz(uint32_t row, uint32_t cb) {
    return row * 128 + (cb ^ ((row & 7) * 16));
}
__device__ __forceinline__ void stcs(float4* p, float4 v) {
    asm volatile("st.global.cs.v4.f32 [%0], {%1,%2,%3,%4};"
                 :: "l"(p), "f"(v.x), "f"(v.y), "f"(v.z), "f"(v.w));
}
__device__ __forceinline__ void wait_flag(const int* f) {
    int v;
    while (true) {
        asm volatile("ld.acquire.gpu.global.b32 %0, [%1];" : "=r"(v) : "l"(f));
        if (v) break;
        __nanosleep(200);
    }
}

// ---------------------------------------------------------------------------
// Fused kernel: GEMM everywhere, output drain fused into enc epilogue.
// (Round-7 structure verbatim; fp16 operands, K=512.)
// ---------------------------------------------------------------------------
__global__ __launch_bounds__(256, 2)
void fused_kernel(const float* __restrict__ bias, float* __restrict__ out) {
    extern __shared__ __align__(1024) char smem[];
    const uint32_t sb = s2u(smem);
    const int bid = blockIdx.x;
    const int tid = threadIdx.x;
    const int lane = tid & 31;
    const int wid  = tid >> 5;
    const int warp_m = wid & 1;     // 32 M rows
    const int warp_n = wid >> 1;    // 32 N cols

    const bool is_pred = (bid < 64);
    int m, n, b;
    const __half *gA, *gB;
    if (is_pred) {
        const int pb = bid >> 4; n = bid & 15;
        gA = g_Ac + (size_t)(1024 + pb * 64) * KC;
        gB = g_Bp + (size_t)(n * 128) * KC;
        m = pb;
        b = pb;
    } else {
        const int e = bid - 64;
        m = e >> 4; n = e & 15;
        gA = g_Ac + (size_t)(m * 64) * KC;
        gB = g_Be + (size_t)(n * 128) * KC;
        b = m >> 2;
    }
    const int vbase = n * 128;

    // ---- cp.async staging precompute ----
    const int ra0 = tid >> 3,         ja0 = (tid & 7) * 16;
    const int ra1 = (tid + 256) >> 3, ja1 = (tid & 7) * 16;
    const uint32_t sA0 = swz(ra0, ja0), sA1 = swz(ra1, ja1);
    int      rb[4], jb[4];
    uint32_t sB[4];
    #pragma unroll
    for (int i = 0; i < 4; i++) {
        int cidx = tid + i * 256;
        rb[i] = cidx >> 3; jb[i] = (cidx & 7) * 16;
        sB[i] = swz(rb[i], jb[i]);
    }

    const int rowA = warp_m * 32 + (lane & 15);
    const uint32_t uA = swz(rowA, (lane >> 4) * 16);
    const int rowB = warp_n * 32 + ((lane >> 4) & 1) * 8 + (lane & 7);
    const uint32_t uB = swz(rowB, ((lane >> 3) & 1) * 16);

    float c[2][4][4];
    #pragma unroll
    for (int i = 0; i < 2; i++)
        #pragma unroll
        for (int j = 0; j < 4; j++)
            #pragma unroll
            for (int e2 = 0; e2 < 4; e2++) c[i][j][e2] = 0.f;

    auto fill = [&](int s, int koff) {
        const uint32_t ab = sb + s * ST_SZ;
        const uint32_t bb = ab + A_ST;
        CPA16(ab + sA0, gA + (size_t)ra0 * KC + koff + ja0 / 2);
        CPA16(ab + sA1, gA + (size_t)ra1 * KC + koff + ja1 / 2);
        #pragma unroll
        for (int i = 0; i < 4; i++)
            CPA16(bb + sB[i], gB + (size_t)rb[i] * KC + koff + jb[i] / 2);
        asm volatile("cp.async.commit_group;");
    };

    fill(0, 0);
    fill(1, BK);

    const int NKT = KC / BK;   // 8
    int s = 0;
    for (int kt = 0; kt < NKT; kt++) {
        if (kt < NKT - 1) asm volatile("cp.async.wait_group 1;");
        else              asm volatile("cp.async.wait_group 0;");
        __syncthreads();

        if (kt + 2 < NKT) {
            int sn = s + 2; if (sn >= STAGES) sn -= STAGES;
            fill(sn, (kt + 2) * BK);
        }

        const uint32_t abase = sb + s * ST_SZ + uA;
        const uint32_t bbase = sb + s * ST_SZ + A_ST + uB;
        #pragma unroll
        for (int kk = 0; kk < 4; kk++) {
            uint32_t a[2][4], bfr[2][4];
            #pragma unroll
            for (int mi = 0; mi < 2; mi++)
                LDSM4(a[mi][0], a[mi][1], a[mi][2], a[mi][3],
                      (abase + mi * 2048) ^ (kk << 5));
            #pragma unroll
            for (int nb = 0; nb < 2; nb++)
                LDSM4(bfr[nb][0], bfr[nb][1], bfr[nb][2], bfr[nb][3],
                      (bbase + nb * 2048) ^ (kk << 5));
            #pragma unroll
            for (int mi = 0; mi < 2; mi++) {
                MMA16816(c[mi][0], a[mi][0], a[mi][1], a[mi][2], a[mi][3], bfr[0][0], bfr[0][1]);
                MMA16816(c[mi][1], a[mi][0], a[mi][1], a[mi][2], a[mi][3], bfr[0][2], bfr[0][3]);
                MMA16816(c[mi][2], a[mi][0], a[mi][1], a[mi][2], a[mi][3], bfr[1][0], bfr[1][1]);
                MMA16816(c[mi][3], a[mi][0], a[mi][1], a[mi][2], a[mi][3], bfr[1][2], bfr[1][3]);
            }
        }
        if (++s >= STAGES) s -= STAGES;
    }

    const int mrow0 = warp_m * 32 + (lane >> 2);
    const int ncol0 = warp_n * 32 + (lane & 3) * 2;

    if (is_pred) {
        // ---- pred epilogue: frags -> g_pred, then release flag ----
        float* C = g_pred + (size_t)(m * 64) * VOCAB + vbase;
        #pragma unroll
        for (int mi = 0; mi < 2; mi++) {
            #pragma unroll
            for (int ni = 0; ni < 4; ni++) {
                float* p0 = &C[(size_t)(mrow0 + mi * 16)     * VOCAB + ncol0 + ni * 8];
                float* p1 = &C[(size_t)(mrow0 + mi * 16 + 8) * VOCAB + ncol0 + ni * 8];
                *(float2*)p0 = make_float2(c[mi][ni][0], c[mi][ni][1]);
                *(float2*)p1 = make_float2(c[mi][ni][2], c[mi][ni][3]);
            }
        }
        __threadfence();
        __syncthreads();
        if (tid == 0) atomicExch(&g_flags[bid], 1);
        return;
    }

    // ---- enc epilogue: frags -> smem, fetch pred tile, drain output ----
    __syncthreads();                       // all LDSM done; safe to reuse smem
    float* enc_s  = (float*)smem;          // [64][PSTR]
    float* pred_s = enc_s + 64 * PSTR;     // [64][PSTR]

    #pragma unroll
    for (int mi = 0; mi < 2; mi++) {
        #pragma unroll
        for (int ni = 0; ni < 4; ni++) {
            float* p0 = &enc_s[(mrow0 + mi * 16)     * PSTR + ncol0 + ni * 8];
            float* p1 = &enc_s[(mrow0 + mi * 16 + 8) * PSTR + ncol0 + ni * 8];
            *(float2*)p0 = make_float2(c[mi][ni][0], c[mi][ni][1]);
            *(float2*)p1 = make_float2(c[mi][ni][2], c[mi][ni][3]);
        }
    }

    if (tid == 0) wait_flag(&g_flags[b * 16 + n]);
    __syncthreads();

    // pred tile + bias -> smem: 64u x 128v = 2048 float4, 8/thread
    {
        const float* pg = g_pred + (size_t)(b * NU) * VOCAB + vbase;
        #pragma unroll
        for (int i = 0; i < 8; i++) {
            int e = tid + i * 256;
            int u = e >> 5, cc = e & 31;
            float4 p = *(const float4*)(pg + (size_t)u * VOCAB + cc * 4);
            float4 bv = *(const float4*)(bias + vbase + cc * 4);
            *(float4*)&pred_s[u * PSTR + cc * 4] =
                make_float4(p.x + bv.x, p.y + bv.y, p.z + bv.z, p.w + bv.w);
        }
    }
    __syncthreads();

    // drain: warp w handles t rows [w*8, w*8+8); per (t,u) row a full warp
    // stores 128 contiguous floats (512B, coalesced).
    const int col   = lane;
    const int tbase = (m & 3) * 64;
    float* ob = out + ((size_t)(b * NT + tbase) * NU) * VOCAB + vbase;

    #pragma unroll
    for (int ti = 0; ti < 8; ti++) {
        const int t = wid * 8 + ti;
        float4 e = *(float4*)&enc_s[t * PSTR + col * 4];
        float4* orow = (float4*)(ob + (size_t)t * NU * VOCAB);
        #pragma unroll 8
        for (int u = 0; u < NU; u++) {
            float4 p = *(float4*)&pred_s[u * PSTR + col * 4];
            stcs(&orow[u * (VOCAB / 4) + col],
                 make_float4(e.x + p.x, e.y + p.y, e.z + p.z, e.w + p.w));
        }
    }
}

// ---------------------------------------------------------------------------
extern "C" void kernel_launch(void* const* d_in, const int* in_sizes, int n_in,
                              void* d_out, int out_size) {
    const float* enc  = (const float*)d_in[0];
    const float* pred = (const float*)d_in[1];
    const float* W    = (const float*)d_in[2];
    const float* bias = (const float*)d_in[3];
    float* out = (float*)d_out;

    cudaFuncSetAttribute(fused_kernel,
                         cudaFuncAttributeMaxDynamicSharedMemorySize, DSMEM);

    convert_kernel<<<5376, 256>>>(enc, pred, W);
    fused_kernel<<<320, 256, DSMEM>>>(bias, out);
}

// round 11
// speedup vs baseline: 1.2230x; 1.0184x over previous
#include <cuda_runtime.h>
#include <cuda_fp16.h>
#include <cstdint>

// RNN-T joint network, ONE launch (grid=256, all co-resident @ occ 2):
//   phase 0: all blocks convert fp32 -> fp16 images (1/256 each), then
//            grid barrier via atomic counter.
//   bid 0..63  : pred GEMM tile 64x128 -> g_pred + release flag, THEN
//                their enc tile + drain (dual-GEMM producers).
//   bid 64..255: enc GEMM tile 64x128 -> smem; wait 1 pred flag; drain
//                2MB output brick with coalesced st.global.cs.
//   end: completion counter; block 0 resets flags/counters for graph replay.

#define VOCAB 2048
#define KC    512
#define NB    4
#define NT    256
#define NU    64
#define GRID  256

// -------- scratch (device globals; no allocations allowed) --------
__device__ __half g_Ac[1280 * KC];      // enc rows 0..1023, pred rows 1024..1279
__device__ __half g_Be[VOCAB * KC];
__device__ __half g_Bp[VOCAB * KC];
__device__ float  g_pred[256 * VOCAB];
__device__ int    g_flags[64];          // pred tile (pb, n): pb*16 + n
__device__ int    g_cvt;                // convert-phase arrival counter
__device__ int    g_done;               // completion counter (for reset)

// ---------------------------------------------------------------------------
// helpers
// ---------------------------------------------------------------------------
#define BK     64
#define STAGES 3
#define A_ST   8192                   // 64 rows * 128B
#define B_ST   16384                  // 128 rows * 128B
#define ST_SZ  (A_ST + B_ST)          // 24KB per stage
#define DSMEM  (STAGES * ST_SZ)       // 72KB (drain needs 67.6KB <= this)
#define PSTR   132                    // padded fp32 row stride for drain tiles

__device__ __forceinline__ uint32_t s2u(const void* p) {
    return (uint32_t)__cvta_generic_to_shared(p);
}
#define CPA16(s, g) asm volatile("cp.async.cg.shared.global [%0], [%1], 16;" :: "r"(s), "l"(g))
#define LDSM4(r0,r1,r2,r3,a) asm volatile( \
    "ldmatrix.sync.aligned.m8n8.x4.shared.b16 {%0,%1,%2,%3}, [%4];" \
    : "=r"(r0),"=r"(r1),"=r"(r2),"=r"(r3) : "r"(a))
#define MMA16816(c,a0,a1,a2,a3,b0,b1) asm volatile( \
    "mma.sync.aligned.m16n8k16.row.col.f32.f16.f16.f32 " \
    "{%0,%1,%2,%3},{%4,%5,%6,%7},{%8,%9},{%0,%1,%2,%3};" \
    : "+f"(c[0]),"+f"(c[1]),"+f"(c[2]),"+f"(c[3]) \
    : "r"(a0),"r"(a1),"r"(a2),"r"(a3),"r"(b0),"r"(b1))

__device__ __forceinline__ uint32_t swz(uint32_t row, uint32_t cb) {
    return row * 128 + (cb ^ ((row & 7) * 16));
}
__device__ __forceinline__ void stcs(float4* p, float4 v) {
    asm volatile("st.global.cs.v4.f32 [%0], {%1,%2,%3,%4};"
                 :: "l"(p), "f"(v.x), "f"(v.y), "f"(v.z), "f"(v.w));
}
__device__ __forceinline__ void wait_flag(const int* f) {
    int v;
    while (true) {
        asm volatile("ld.acquire.gpu.global.b32 %0, [%1];" : "=r"(v) : "l"(f));
        if (v) break;
        __nanosleep(200);
    }
}
__device__ __forceinline__ void wait_cnt(const int* f, int target) {
    int v;
    while (true) {
        asm volatile("ld.acquire.gpu.global.b32 %0, [%1];" : "=r"(v) : "l"(f));
        if (v == target) break;
        __nanosleep(64);
    }
}

// ---------------------------------------------------------------------------
// phase 0: one float2 -> half2 element
// ---------------------------------------------------------------------------
__device__ __forceinline__ void cvt_one(int idx,
                                        const float* __restrict__ enc,
                                        const float* __restrict__ pred,
                                        const float* __restrict__ W) {
    float2 x;
    __half* base;
    if (idx < 262144) {                       // enc: 1024 rows x 256 pairs
        x = ((const float2*)enc)[idx];
        int m = idx >> 8, k = (idx & 255) * 2;
        base = g_Ac + (size_t)m * KC + k;
    } else if (idx < 327680) {                // pred: 256 rows x 256 pairs
        int p = idx - 262144;
        x = ((const float2*)pred)[p];
        int m = 1024 + (p >> 8), k = (p & 255) * 2;
        base = g_Ac + (size_t)m * KC + k;
    } else {                                  // W: 2048 rows x 512 pairs
        int p = idx - 327680;
        x = ((const float2*)W)[p];
        int v = p >> 9, k = (p & 511) * 2;
        base = (k < 512) ? (g_Be + (size_t)v * KC + k)
                         : (g_Bp + (size_t)v * KC + (k - 512));
    }
    *(__half2*)base = __floats2half2_rn(x.x, x.y);
}

// ---------------------------------------------------------------------------
// one 64x128 fp16 GEMM tile, K=512 (proven R10 mainloop)
// ---------------------------------------------------------------------------
__device__ __forceinline__ void gemm_tile(uint32_t sb, int tid, int lane,
                                          int warp_m, int warp_n,
                                          const __half* __restrict__ gA,
                                          const __half* __restrict__ gB,
                                          float (&c)[2][4][4]) {
    #pragma unroll
    for (int i = 0; i < 2; i++)
        #pragma unroll
        for (int j = 0; j < 4; j++)
            #pragma unroll
            for (int e2 = 0; e2 < 4; e2++) c[i][j][e2] = 0.f;

    const int ra0 = tid >> 3,         ja0 = (tid & 7) * 16;
    const int ra1 = (tid + 256) >> 3;
    const uint32_t sA0 = swz(ra0, ja0), sA1 = swz(ra1, ja0);
    int      rb[4], jb[4];
    uint32_t sB[4];
    #pragma unroll
    for (int i = 0; i < 4; i++) {
        int cidx = tid + i * 256;
        rb[i] = cidx >> 3; jb[i] = (cidx & 7) * 16;
        sB[i] = swz(rb[i], jb[i]);
    }

    const int rowA = warp_m * 32 + (lane & 15);
    const uint32_t uA = swz(rowA, (lane >> 4) * 16);
    const int rowB = warp_n * 32 + ((lane >> 4) & 1) * 8 + (lane & 7);
    const uint32_t uB = swz(rowB, ((lane >> 3) & 1) * 16);

    auto fill = [&](int s, int koff) {
        const uint32_t ab = sb + s * ST_SZ;
        const uint32_t bb = ab + A_ST;
        CPA16(ab + sA0, gA + (size_t)ra0 * KC + koff + ja0 / 2);
        CPA16(ab + sA1, gA + (size_t)ra1 * KC + koff + ja0 / 2);
        #pragma unroll
        for (int i = 0; i < 4; i++)
            CPA16(bb + sB[i], gB + (size_t)rb[i] * KC + koff + jb[i] / 2);
        asm volatile("cp.async.commit_group;");
    };

    fill(0, 0);
    fill(1, BK);

    const int NKT = KC / BK;   // 8
    int s = 0;
    for (int kt = 0; kt < NKT; kt++) {
        if (kt < NKT - 1) asm volatile("cp.async.wait_group 1;");
        else              asm volatile("cp.async.wait_group 0;");
        __syncthreads();

        if (kt + 2 < NKT) {
            int sn = s + 2; if (sn >= STAGES) sn -= STAGES;
            fill(sn, (kt + 2) * BK);
        }

        const uint32_t abase = sb + s * ST_SZ + uA;
        const uint32_t bbase = sb + s * ST_SZ + A_ST + uB;
        #pragma unroll
        for (int kk = 0; kk < 4; kk++) {
            uint32_t a[2][4], bfr[2][4];
            #pragma unroll
            for (int mi = 0; mi < 2; mi++)
                LDSM4(a[mi][0], a[mi][1], a[mi][2], a[mi][3],
                      (abase + mi * 2048) ^ (kk << 5));
            #pragma unroll
            for (int nb = 0; nb < 2; nb++)
                LDSM4(bfr[nb][0], bfr[nb][1], bfr[nb][2], bfr[nb][3],
                      (bbase + nb * 2048) ^ (kk << 5));
            #pragma unroll
            for (int mi = 0; mi < 2; mi++) {
                MMA16816(c[mi][0], a[mi][0], a[mi][1], a[mi][2], a[mi][3], bfr[0][0], bfr[0][1]);
                MMA16816(c[mi][1], a[mi][0], a[mi][1], a[mi][2], a[mi][3], bfr[0][2], bfr[0][3]);
                MMA16816(c[mi][2], a[mi][0], a[mi][1], a[mi][2], a[mi][3], bfr[1][0], bfr[1][1]);
                MMA16816(c[mi][3], a[mi][0], a[mi][1], a[mi][2], a[mi][3], bfr[1][2], bfr[1][3]);
            }
        }
        if (++s >= STAGES) s -= STAGES;
    }
    __syncthreads();   // smem free for next use
}

// ---------------------------------------------------------------------------
// Fused kernel: convert + barrier, GEMM(s), drain. Grid 256, one wave.
// ---------------------------------------------------------------------------
__global__ __launch_bounds__(256, 2)
void fused_kernel(const float* __restrict__ enc_in,
                  const float* __restrict__ pred_in,
                  const float* __restrict__ W,
                  const float* __restrict__ bias,
                  float* __restrict__ out) {
    extern __shared__ __align__(1024) char smem[];
    const uint32_t sb = s2u(smem);
    const int bid = blockIdx.x;
    const int tid = threadIdx.x;
    const int lane = tid & 31;
    const int wid  = tid >> 5;
    const int warp_m = wid & 1;     // 32 M rows
    const int warp_n = wid >> 1;    // 32 N cols

    // ---------- phase 0: convert (1376256 pairs / 256 blocks = 21/thr) ----
    #pragma unroll
    for (int i = 0; i < 21; i++)
        cvt_one(bid * 256 + tid + i * 65536, enc_in, pred_in, W);
    __threadfence();
    __syncthreads();
    if (tid == 0) {
        atomicAdd(&g_cvt, 1);
        wait_cnt(&g_cvt, GRID);
    }
    __syncthreads();

    // ---------- roles ----------
    const int m = bid >> 4, n = bid & 15;     // enc tile coords
    const int b = m >> 2;
    const int vbase = n * 128;

    float c[2][4][4];
    const int mrow0 = warp_m * 32 + (lane >> 2);
    const int ncol0 = warp_n * 32 + (lane & 3) * 2;

    if (bid < 64) {
        // ---- pred GEMM first: tile (pb = m, n) ----
        gemm_tile(sb, tid, lane, warp_m, warp_n,
                  g_Ac + (size_t)(1024 + m * 64) * KC,
                  g_Bp + (size_t)(n * 128) * KC, c);
        float* C = g_pred + (size_t)(m * 64) * VOCAB + vbase;
        #pragma unroll
        for (int mi = 0; mi < 2; mi++) {
            #pragma unroll
            for (int ni = 0; ni < 4; ni++) {
                float* p0 = &C[(size_t)(mrow0 + mi * 16)     * VOCAB + ncol0 + ni * 8];
                float* p1 = &C[(size_t)(mrow0 + mi * 16 + 8) * VOCAB + ncol0 + ni * 8];
                *(float2*)p0 = make_float2(c[mi][ni][0], c[mi][ni][1]);
                *(float2*)p1 = make_float2(c[mi][ni][2], c[mi][ni][3]);
            }
        }
        __threadfence();
        __syncthreads();
        if (tid == 0) atomicExch(&g_flags[m * 16 + n], 1);
    }

    // ---- enc GEMM: tile (m, n) ----
    gemm_tile(sb, tid, lane, warp_m, warp_n,
              g_Ac + (size_t)(m * 64) * KC,
              g_Be + (size_t)(n * 128) * KC, c);

    // ---- enc epilogue: frags -> smem, fetch pred tile, drain output ----
    float* enc_s  = (float*)smem;          // [64][PSTR]
    float* pred_s = enc_s + 64 * PSTR;     // [64][PSTR]

    #pragma unroll
    for (int mi = 0; mi < 2; mi++) {
        #pragma unroll
        for (int ni = 0; ni < 4; ni++) {
            float* p0 = &enc_s[(mrow0 + mi * 16)     * PSTR + ncol0 + ni * 8];
            float* p1 = &enc_s[(mrow0 + mi * 16 + 8) * PSTR + ncol0 + ni * 8];
            *(float2*)p0 = make_float2(c[mi][ni][0], c[mi][ni][1]);
            *(float2*)p1 = make_float2(c[mi][ni][2], c[mi][ni][3]);
        }
    }

    if (tid == 0) wait_flag(&g_flags[b * 16 + n]);
    __syncthreads();

    // pred tile + bias -> smem: 64u x 128v = 2048 float4, 8/thread
    {
        const float* pg = g_pred + (size_t)(b * NU) * VOCAB + vbase;
        #pragma unroll
        for (int i = 0; i < 8; i++) {
            int e = tid + i * 256;
            int u = e >> 5, cc = e & 31;
            float4 p = *(const float4*)(pg + (size_t)u * VOCAB + cc * 4);
            float4 bv = *(const float4*)(bias + vbase + cc * 4);
            *(float4*)&pred_s[u * PSTR + cc * 4] =
                make_float4(p.x + bv.x, p.y + bv.y, p.z + bv.z, p.w + bv.w);
        }
    }
    __syncthreads();

    // drain: warp w handles t rows [w*8, w*8+8); per (t,u) row a full warp
    // stores 128 contiguous floats (512B, coalesced).
    const int col   = lane;
    const int tbase = (m & 3) * 64;
    float* ob = out + ((size_t)(b * NT + tbase) * NU) * VOCAB + vbase;

    #pragma unroll
    for (int ti = 0; ti < 8; ti++) {
        const int t = wid * 8 + ti;
        float4 e = *(float4*)&enc_s[t * PSTR + col * 4];
        float4* orow = (float4*)(ob + (size_t)t * NU * VOCAB);
        #pragma unroll 8
        for (int u = 0; u < NU; u++) {
            float4 p = *(float4*)&pred_s[u * PSTR + col * 4];
            stcs(&orow[u * (VOCAB / 4) + col],
                 make_float4(e.x + p.x, e.y + p.y, e.z + p.z, e.w + p.w));
        }
    }

    // ---------- completion + reset (graph-replay correctness) ----------
    __syncthreads();
    if (tid == 0) {
        __threadfence();
        atomicAdd(&g_done, 1);
        if (bid == 0) {
            wait_cnt(&g_done, GRID);
            #pragma unroll
            for (int i = 0; i < 64; i++) g_flags[i] = 0;
            g_cvt = 0;
            g_done = 0;
            __threadfence();
        }
    }
}

// ---------------------------------------------------------------------------
extern "C" void kernel_launch(void* const* d_in, const int* in_sizes, int n_in,
                              void* d_out, int out_size) {
    const float* enc  = (const float*)d_in[0];
    const float* pred = (const float*)d_in[1];
    const float* W    = (const float*)d_in[2];
    const float* bias = (const float*)d_in[3];
    float* out = (float*)d_out;

    cudaFuncSetAttribute(fused_kernel,
                         cudaFuncAttributeMaxDynamicSharedMemorySize, DSMEM);

    fused_kernel<<<GRID, 256, DSMEM>>>(enc, pred, W, bias, out);
}

// round 12
// speedup vs baseline: 1.2316x; 1.0070x over previous
#include <cuda_runtime.h>
#include <cuda_fp16.h>
#include <cstdint>

// RNN-T joint network, ONE launch (grid=256, all co-resident @ occ 2):
//   0a: ALL blocks convert pred + W_pred (fp32->fp16), barrier c1 (256).
//   then: bids 0..63 run pred GEMM 64x128 -> g_pred + flag   (overlapped
//         with) bids 64..255 converting enc + W_enc; barrier c2 (192).
//   all: enc GEMM 64x128 -> smem; wait 1 pred flag (normally pre-set);
//        drain 2MB output brick with coalesced st.global.cs.
//   end: completion counter; block 0 resets flags/counters (graph replay).

#define VOCAB 2048
#define KC    512
#define NB    4
#define NT    256
#define NU    64
#define GRID  256
#define NDUAL 64

// -------- scratch (device globals; no allocations allowed) --------
__device__ __half g_Ac[1280 * KC];      // enc rows 0..1023, pred rows 1024..1279
__device__ __half g_Be[VOCAB * KC];
__device__ __half g_Bp[VOCAB * KC];
__device__ float  g_pred[256 * VOCAB];
__device__ int    g_flags[64];          // pred tile (pb, n): pb*16 + n
__device__ int    g_c1;                 // 0a barrier (target 256)
__device__ int    g_c2;                 // 0b barrier (target 192)
__device__ int    g_done;               // completion counter (for reset)

// ---------------------------------------------------------------------------
// helpers
// ---------------------------------------------------------------------------
#define BK     64
#define STAGES 3
#define A_ST   8192                   // 64 rows * 128B
#define B_ST   16384                  // 128 rows * 128B
#define ST_SZ  (A_ST + B_ST)          // 24KB per stage
#define DSMEM  (STAGES * ST_SZ)       // 72KB (drain needs 67.6KB <= this)
#define PSTR   132                    // padded fp32 row stride for drain tiles

__device__ __forceinline__ uint32_t s2u(const void* p) {
    return (uint32_t)__cvta_generic_to_shared(p);
}
#define CPA16(s, g) asm volatile("cp.async.cg.shared.global [%0], [%1], 16;" :: "r"(s), "l"(g))
#define LDSM4(r0,r1,r2,r3,a) asm volatile( \
    "ldmatrix.sync.aligned.m8n8.x4.shared.b16 {%0,%1,%2,%3}, [%4];" \
    : "=r"(r0),"=r"(r1),"=r"(r2),"=r"(r3) : "r"(a))
#define MMA16816(c,a0,a1,a2,a3,b0,b1) asm volatile( \
    "mma.sync.aligned.m16n8k16.row.col.f32.f16.f16.f32 " \
    "{%0,%1,%2,%3},{%4,%5,%6,%7},{%8,%9},{%0,%1,%2,%3};" \
    : "+f"(c[0]),"+f"(c[1]),"+f"(c[2]),"+f"(c[3]) \
    : "r"(a0),"r"(a1),"r"(a2),"r"(a3),"r"(b0),"r"(b1))

__device__ __forceinline__ uint32_t swz(uint32_t row, uint32_t cb) {
    return row * 128 + (cb ^ ((row & 7) * 16));
}
__device__ __forceinline__ void stcs(float4* p, float4 v) {
    asm volatile("st.global.cs.v4.f32 [%0], {%1,%2,%3,%4};"
                 :: "l"(p), "f"(v.x), "f"(v.y), "f"(v.z), "f"(v.w));
}
__device__ __forceinline__ void wait_flag(const int* f) {
    int v;
    while (true) {
        asm volatile("ld.acquire.gpu.global.b32 %0, [%1];" : "=r"(v) : "l"(f));
        if (v) break;
        __nanosleep(128);
    }
}
__device__ __forceinline__ void wait_cnt(const int* f, int target) {
    int v;
    while (true) {
        asm volatile("ld.acquire.gpu.global.b32 %0, [%1];" : "=r"(v) : "l"(f));
        if (v == target) break;
        __nanosleep(64);
    }
}

// ---------------------------------------------------------------------------
// one 64x128 fp16 GEMM tile, K=512 (proven R10/R11 mainloop)
// ---------------------------------------------------------------------------
__device__ __forceinline__ void gemm_tile(uint32_t sb, int tid, int lane,
                                          int warp_m, int warp_n,
                                          const __half* __restrict__ gA,
                                          const __half* __restrict__ gB,
                                          float (&c)[2][4][4]) {
    #pragma unroll
    for (int i = 0; i < 2; i++)
        #pragma unroll
        for (int j = 0; j < 4; j++)
            #pragma unroll
            for (int e2 = 0; e2 < 4; e2++) c[i][j][e2] = 0.f;

    const int ra0 = tid >> 3,         ja0 = (tid & 7) * 16;
    const int ra1 = (tid + 256) >> 3;
    const uint32_t sA0 = swz(ra0, ja0), sA1 = swz(ra1, ja0);
    int      rb[4], jb[4];
    uint32_t sB[4];
    #pragma unroll
    for (int i = 0; i < 4; i++) {
        int cidx = tid + i * 256;
        rb[i] = cidx >> 3; jb[i] = (cidx & 7) * 16;
        sB[i] = swz(rb[i], jb[i]);
    }

    const int rowA = warp_m * 32 + (lane & 15);
    const uint32_t uA = swz(rowA, (lane >> 4) * 16);
    const int rowB = warp_n * 32 + ((lane >> 4) & 1) * 8 + (lane & 7);
    const uint32_t uB = swz(rowB, ((lane >> 3) & 1) * 16);

    auto fill = [&](int s, int koff) {
        const uint32_t ab = sb + s * ST_SZ;
        const uint32_t bb = ab + A_ST;
        CPA16(ab + sA0, gA + (size_t)ra0 * KC + koff + ja0 / 2);
        CPA16(ab + sA1, gA + (size_t)ra1 * KC + koff + ja0 / 2);
        #pragma unroll
        for (int i = 0; i < 4; i++)
            CPA16(bb + sB[i], gB + (size_t)rb[i] * KC + koff + jb[i] / 2);
        asm volatile("cp.async.commit_group;");
    };

    fill(0, 0);
    fill(1, BK);

    const int NKT = KC / BK;   // 8
    int s = 0;
    for (int kt = 0; kt < NKT; kt++) {
        if (kt < NKT - 1) asm volatile("cp.async.wait_group 1;");
        else              asm volatile("cp.async.wait_group 0;");
        __syncthreads();

        if (kt + 2 < NKT) {
            int sn = s + 2; if (sn >= STAGES) sn -= STAGES;
            fill(sn, (kt + 2) * BK);
        }

        const uint32_t abase = sb + s * ST_SZ + uA;
        const uint32_t bbase = sb + s * ST_SZ + A_ST + uB;
        #pragma unroll
        for (int kk = 0; kk < 4; kk++) {
            uint32_t a[2][4], bfr[2][4];
            #pragma unroll
            for (int mi = 0; mi < 2; mi++)
                LDSM4(a[mi][0], a[mi][1], a[mi][2], a[mi][3],
                      (abase + mi * 2048) ^ (kk << 5));
            #pragma unroll
            for (int nb = 0; nb < 2; nb++)
                LDSM4(bfr[nb][0], bfr[nb][1], bfr[nb][2], bfr[nb][3],
                      (bbase + nb * 2048) ^ (kk << 5));
            #pragma unroll
            for (int mi = 0; mi < 2; mi++) {
                MMA16816(c[mi][0], a[mi][0], a[mi][1], a[mi][2], a[mi][3], bfr[0][0], bfr[0][1]);
                MMA16816(c[mi][1], a[mi][0], a[mi][1], a[mi][2], a[mi][3], bfr[0][2], bfr[0][3]);
                MMA16816(c[mi][2], a[mi][0], a[mi][1], a[mi][2], a[mi][3], bfr[1][0], bfr[1][1]);
                MMA16816(c[mi][3], a[mi][0], a[mi][1], a[mi][2], a[mi][3], bfr[1][2], bfr[1][3]);
            }
        }
        if (++s >= STAGES) s -= STAGES;
    }
    __syncthreads();   // smem free for next use
}

// ---------------------------------------------------------------------------
// Fused kernel: split-phase convert, pred GEMM overlapped with enc convert.
// ---------------------------------------------------------------------------
__global__ __launch_bounds__(256, 2)
void fused_kernel(const float* __restrict__ enc_in,
                  const float* __restrict__ pred_in,
                  const float* __restrict__ W,
                  const float* __restrict__ bias,
                  float* __restrict__ out) {
    extern __shared__ __align__(1024) char smem[];
    const uint32_t sb = s2u(smem);
    const int bid = blockIdx.x;
    const int tid = threadIdx.x;
    const int lane = tid & 31;
    const int wid  = tid >> 5;
    const int warp_m = wid & 1;     // 32 M rows
    const int warp_n = wid >> 1;    // 32 N cols

    // ---------- phase 0a: convert pred + W_pred (all 256 blocks) ----------
    {
        const int base = bid * 256 + tid;        // 0..65535
        // pred: 65536 float2 pairs (1/thread)
        {
            float2 x = ((const float2*)pred_in)[base];
            int mm = 1024 + (base >> 8), k2 = (base & 255) * 2;
            *(__half2*)(g_Ac + (size_t)mm * KC + k2) = __floats2half2_rn(x.x, x.y);
        }
        // W_pred half: 524288 pairs (8/thread). W row = 512 pairs; Bp = pairs 256..511.
        #pragma unroll
        for (int j = 0; j < 8; j++) {
            int q = base + j * 65536;            // 0..524287
            int v = q >> 8, kp = q & 255;
            float2 x = ((const float2*)W)[(size_t)v * 512 + 256 + kp];
            *(__half2*)(g_Bp + (size_t)v * KC + kp * 2) = __floats2half2_rn(x.x, x.y);
        }
    }
    __threadfence();
    __syncthreads();
    if (tid == 0) atomicAdd(&g_c1, 1);

    const int m = bid >> 4, n = bid & 15;     // enc tile coords
    const int b = m >> 2;
    const int vbase = n * 128;

    float c[2][4][4];
    const int mrow0 = warp_m * 32 + (lane >> 2);
    const int ncol0 = warp_n * 32 + (lane & 3) * 2;

    if (bid < NDUAL) {
        // ---------- dual blocks: pred GEMM (tile pb=m, n), overlapped ----
        if (tid == 0) wait_cnt(&g_c1, GRID);
        __syncthreads();
        gemm_tile(sb, tid, lane, warp_m, warp_n,
                  g_Ac + (size_t)(1024 + m * 64) * KC,
                  g_Bp + (size_t)(n * 128) * KC, c);
        float* C = g_pred + (size_t)(m * 64) * VOCAB + vbase;
        #pragma unroll
        for (int mi = 0; mi < 2; mi++) {
            #pragma unroll
            for (int ni = 0; ni < 4; ni++) {
                float* p0 = &C[(size_t)(mrow0 + mi * 16)     * VOCAB + ncol0 + ni * 8];
                float* p1 = &C[(size_t)(mrow0 + mi * 16 + 8) * VOCAB + ncol0 + ni * 8];
                *(float2*)p0 = make_float2(c[mi][ni][0], c[mi][ni][1]);
                *(float2*)p1 = make_float2(c[mi][ni][2], c[mi][ni][3]);
            }
        }
        __threadfence();
        __syncthreads();
        if (tid == 0) {
            atomicExch(&g_flags[m * 16 + n], 1);
            wait_cnt(&g_c2, GRID - NDUAL);      // enc/Be images ready?
        }
        __syncthreads();
    } else {
        // ---------- other blocks: phase 0b convert enc + W_enc -----------
        const int lid = bid - NDUAL;             // 0..191
        const int base = lid * 256 + tid;
        #pragma unroll
        for (int j = 0; j < 16; j++) {
            int t = base + j * 49152;            // 0..786431
            if (t < 262144) {                    // enc: 1024 rows x 256 pairs
                float2 x = ((const float2*)enc_in)[t];
                int mm = t >> 8, k2 = (t & 255) * 2;
                *(__half2*)(g_Ac + (size_t)mm * KC + k2) = __floats2half2_rn(x.x, x.y);
            } else {                             // W_enc half: pairs 0..255 per row
                int q = t - 262144;              // 0..524287
                int v = q >> 8, kp = q & 255;
                float2 x = ((const float2*)W)[(size_t)v * 512 + kp];
                *(__half2*)(g_Be + (size_t)v * KC + kp * 2) = __floats2half2_rn(x.x, x.y);
            }
        }
        __threadfence();
        __syncthreads();
        if (tid == 0) {
            atomicAdd(&g_c2, 1);
            wait_cnt(&g_c2, GRID - NDUAL);
        }
        __syncthreads();
    }

    // ---------- enc GEMM: tile (m, n) ----------
    gemm_tile(sb, tid, lane, warp_m, warp_n,
              g_Ac + (size_t)(m * 64) * KC,
              g_Be + (size_t)(n * 128) * KC, c);

    // ---------- enc epilogue: frags -> smem, fetch pred tile, drain ------
    float* enc_s  = (float*)smem;          // [64][PSTR]
    float* pred_s = enc_s + 64 * PSTR;     // [64][PSTR]

    #pragma unroll
    for (int mi = 0; mi < 2; mi++) {
        #pragma unroll
        for (int ni = 0; ni < 4; ni++) {
            float* p0 = &enc_s[(mrow0 + mi * 16)     * PSTR + ncol0 + ni * 8];
            float* p1 = &enc_s[(mrow0 + mi * 16 + 8) * PSTR + ncol0 + ni * 8];
            *(float2*)p0 = make_float2(c[mi][ni][0], c[mi][ni][1]);
            *(float2*)p1 = make_float2(c[mi][ni][2], c[mi][ni][3]);
        }
    }

    if (tid == 0) wait_flag(&g_flags[b * 16 + n]);
    __syncthreads();

    // pred tile + bias -> smem: 64u x 128v = 2048 float4, 8/thread
    {
        const float* pg = g_pred + (size_t)(b * NU) * VOCAB + vbase;
        #pragma unroll
        for (int i = 0; i < 8; i++) {
            int e = tid + i * 256;
            int u = e >> 5, cc = e & 31;
            float4 p = *(const float4*)(pg + (size_t)u * VOCAB + cc * 4);
            float4 bv = *(const float4*)(bias + vbase + cc * 4);
            *(float4*)&pred_s[u * PSTR + cc * 4] =
                make_float4(p.x + bv.x, p.y + bv.y, p.z + bv.z, p.w + bv.w);
        }
    }
    __syncthreads();

    // drain: warp w handles t rows [w*8, w*8+8); per (t,u) row a full warp
    // stores 128 contiguous floats (512B, coalesced).
    const int col   = lane;
    const int tbase = (m & 3) * 64;
    float* ob = out + ((size_t)(b * NT + tbase) * NU) * VOCAB + vbase;

    #pragma unroll
    for (int ti = 0; ti < 8; ti++) {
        const int t = wid * 8 + ti;
        float4 e = *(float4*)&enc_s[t * PSTR + col * 4];
        float4* orow = (float4*)(ob + (size_t)t * NU * VOCAB);
        #pragma unroll 8
        for (int u = 0; u < NU; u++) {
            float4 p = *(float4*)&pred_s[u * PSTR + col * 4];
            stcs(&orow[u * (VOCAB / 4) + col],
                 make_float4(e.x + p.x, e.y + p.y, e.z + p.z, e.w + p.w));
        }
    }

    // ---------- completion + reset (graph-replay correctness) ----------
    __syncthreads();
    if (tid == 0) {
        __threadfence();
        atomicAdd(&g_done, 1);
        if (bid == 0) {
            wait_cnt(&g_done, GRID);
            #pragma unroll
            for (int i = 0; i < 64; i++) g_flags[i] = 0;
            g_c1 = 0;
            g_c2 = 0;
            g_done = 0;
            __threadfence();
        }
    }
}

// ---------------------------------------------------------------------------
extern "C" void kernel_launch(void* const* d_in, const int* in_sizes, int n_in,
                              void* d_out, int out_size) {
    const float* enc  = (const float*)d_in[0];
    const float* pred = (const float*)d_in[1];
    const float* W    = (const float*)d_in[2];
    const float* bias = (const float*)d_in[3];
    float* out = (float*)d_out;

    cudaFuncSetAttribute(fused_kernel,
                         cudaFuncAttributeMaxDynamicSharedMemorySize, DSMEM);

    fused_kernel<<<GRID, 256, DSMEM>>>(enc, pred, W, bias, out);
}